// round 11
// baseline (speedup 1.0000x reference)
#include <cuda_runtime.h>
#include <math.h>

#define N_AG 262144
#define GRID_SZ 1024
#define NCELL (GRID_SZ*GRID_SZ)
#define NCH 8
#define HID 64
#define DT 0.1f
#define DECAY 0.99f
#define SENSOR_LEN 3.0f
// cos(0.6), sin(0.6)
#define COS_A 0.825335614909678f
#define SIN_A 0.564642473395035f

typedef unsigned long long ull;

// Scratch (__device__ globals; no allocation allowed)
__device__ int    g_claim[NCELL];        // 4 MB : winning agent id per cell (reset by winners)
__device__ float4 g_boxA[NCELL];         // 16 MB: 3x3 box sums, channels 0-3
__device__ float4 g_boxB[NCELL];         // 16 MB: 3x3 box sums, channels 4-7

__device__ __forceinline__ ull pk2(float lo, float hi) {
    ull r; asm("mov.b64 %0, {%1, %2};" : "=l"(r) : "f"(lo), "f"(hi)); return r;
}
__device__ __forceinline__ void upk2(ull v, float& lo, float& hi) {
    asm("mov.b64 {%0, %1}, %2;" : "=f"(lo), "=f"(hi) : "l"(v));
}
__device__ __forceinline__ ull fma2(ull a, ull b, ull c) {
    ull d; asm("fma.rn.f32x2 %0, %1, %2, %3;" : "=l"(d) : "l"(a), "l"(b), "l"(c)); return d;
}

// Pass 0: block = one lattice row. Coalesced float4 loads -> column sums in smem,
// decayed output, coalesced box-sum stores (stride-256 cell remap).
// Also: this thread claims agent tid's deposit cell (atomicMax, last-id-wins).
__global__ __launch_bounds__(256) void prep_kernel(const float* __restrict__ lat,
                                                   const float* __restrict__ pos,
                                                   float* __restrict__ out_lat) {
    __shared__ float cs_s[NCH][GRID_SZ];
    int x = blockIdx.x;
    int t = threadIdx.x;
    int y0 = t << 2;
    int r0 = ((x + 1023) & 1023) << 10;
    int r1 = x << 10;
    int r2 = ((x + 1) & 1023) << 10;

    // agent claim (one agent per prep thread; coalesced pos read)
    int a = blockIdx.x * 256 + t;
    float pax = pos[a], pay = pos[N_AG + a];
    int ca = ((((int)rintf(pax)) & 1023) << 10) | (((int)rintf(pay)) & 1023);
    atomicMax(&g_claim[ca], a);

#pragma unroll
    for (int c = 0; c < NCH; c++) {
        const float* L = lat + ((size_t)c << 20);
        float4 va = __ldg((const float4*)&L[r0 | y0]);
        float4 vb = __ldg((const float4*)&L[r1 | y0]);
        float4 vd = __ldg((const float4*)&L[r2 | y0]);
        *reinterpret_cast<float4*>(&cs_s[c][y0]) =
            make_float4(va.x + vb.x + vd.x, va.y + vb.y + vd.y,
                        va.z + vb.z + vd.z, va.w + vb.w + vd.w);
        *reinterpret_cast<float4*>(&out_lat[((size_t)c << 20) | (r1 | y0)]) =
            make_float4(vb.x * DECAY, vb.y * DECAY, vb.z * DECAY, vb.w * DECAY);
    }
    __syncthreads();

#pragma unroll
    for (int i = 0; i < 4; i++) {
        int y  = t + (i << 8);               // stride-256 cell ownership
        int ym = (y + 1023) & 1023;
        int yp = (y + 1) & 1023;
        float v[NCH];
#pragma unroll
        for (int c = 0; c < NCH; c++)
            v[c] = cs_s[c][ym] + cs_s[c][y] + cs_s[c][yp];
        int cell = r1 | y;
        g_boxA[cell] = make_float4(v[0], v[1], v[2], v[3]);   // 16B lane stride
        g_boxB[cell] = make_float4(v[4], v[5], v[6], v[7]);
    }
}

// Pass 1: one agent per thread. Scheduling: gathers + claim check + cur
// prefetch issued BEFORE weight staging/sync and MLP, so all scattered-load
// latency hides under compute. Tail is stores only.
__global__ __launch_bounds__(256, 3) void agent_kernel(
    const float* __restrict__ pos, const float* __restrict__ vel,
    const float* __restrict__ W1, const float* __restrict__ b1,
    const float* __restrict__ W2, const float* __restrict__ b2,
    const float* __restrict__ lat, float* __restrict__ out) {
    __shared__ float sW1[24 * HID];    // row-major [k][j]: natural (w_j,w_j+1) pairs
    __shared__ float sW2p[HID * 12];   // padded [j][12]
    __shared__ float sb1[HID];
    __shared__ float sO0[12];
    int t = threadIdx.x;
    int i = blockIdx.x * 256 + t;

    // ---- agent state + sensor cells, gathers in flight ASAP ----
    float px = pos[i], py = pos[N_AG + i];
    float vx = vel[i], vy = vel[N_AG + i];

    float invn = rsqrtf(fmaf(vx, vx, vy * vy));
    float c0 = vx * invn, s0 = vy * invn;
    float csv[3], snv[3];
    csv[0] = c0;                        snv[0] = s0;
    csv[1] = c0 * COS_A - s0 * SIN_A;   snv[1] = s0 * COS_A + c0 * SIN_A;
    csv[2] = c0 * COS_A + s0 * SIN_A;   snv[2] = s0 * COS_A - c0 * SIN_A;

    float4 gA[3], gB[3];
#pragma unroll
    for (int s = 0; s < 3; s++) {
        int cx = (int)rintf(fmaf(SENSOR_LEN, csv[s], px));
        int cy = (int)rintf(fmaf(SENSOR_LEN, snv[s], py));
        int scell = ((cx & (GRID_SZ - 1)) << 10) | (cy & (GRID_SZ - 1));
        gA[s] = __ldg(&g_boxA[scell]);
        gB[s] = __ldg(&g_boxB[scell]);
    }

    // ---- deposit prefetch: own cell, win check, cur loads (predicated) ----
    int cell = ((((int)rintf(px)) & 1023) << 10) | (((int)rintf(py)) & 1023);
    bool win = (g_claim[cell] == i);     // loser sees winner_id or -1, never i
    float cur[NCH];
#pragma unroll
    for (int c = 0; c < NCH; c++)
        cur[c] = win ? __ldg(&lat[(c << 20) | cell]) : 0.f;

    // ---- weight staging (gathers/cur latency hides under this) ----
    for (int q = t; q < 24 * HID; q += 256) sW1[q] = W1[q];
    for (int q = t; q < HID * 12; q += 256) { int j = q / 12, k = q - j * 12; sW2p[q] = (k < 10) ? W2[j * 10 + k] : 0.f; }
    if (t < HID) sb1[t] = b1[t];
    if (t < 12)  sO0[t] = (t < 10) ? b2[t] : 0.f;
    __syncthreads();

    float xa[24];
#pragma unroll
    for (int s = 0; s < 3; s++) {
        xa[s * 8 + 0] = gA[s].x; xa[s * 8 + 1] = gA[s].y; xa[s * 8 + 2] = gA[s].z; xa[s * 8 + 3] = gA[s].w;
        xa[s * 8 + 4] = gB[s].x; xa[s * 8 + 5] = gB[s].y; xa[s * 8 + 6] = gB[s].z; xa[s * 8 + 7] = gB[s].w;
    }

    // ---- MLP: 4 hidden units per block iter, f32x2 pairs ----
    ull o2[6];
#pragma unroll
    for (int k = 0; k < 6; k++) o2[k] = pk2(sO0[2 * k], sO0[2 * k + 1]);

#pragma unroll 1
    for (int j = 0; j < HID; j += 4) {
        ulonglong2 bu = *reinterpret_cast<const ulonglong2*>(&sb1[j]);
        ull a01 = bu.x, a23 = bu.y;
#pragma unroll
        for (int k = 0; k < 24; k++) {
            ulonglong2 wu = *reinterpret_cast<const ulonglong2*>(&sW1[k * HID + j]);
            ull x2 = pk2(xa[k], xa[k]);          // ALU-pipe mov, overlaps FMA
            a01 = fma2(x2, wu.x, a01);
            a23 = fma2(x2, wu.y, a23);
        }
        float hv[4];
        upk2(a01, hv[0], hv[1]);
        upk2(a23, hv[2], hv[3]);
#pragma unroll
        for (int jj = 0; jj < 4; jj++) {
            float h;
            asm("tanh.approx.f32 %0, %1;" : "=f"(h) : "f"(hv[jj]));
            ull h2 = pk2(h, h);
            const ulonglong2* wp = reinterpret_cast<const ulonglong2*>(&sW2p[(j + jj) * 12]);
            ulonglong2 u0 = wp[0], u1 = wp[1], u2 = wp[2];
            o2[0] = fma2(h2, u0.x, o2[0]); o2[1] = fma2(h2, u0.y, o2[1]);
            o2[2] = fma2(h2, u1.x, o2[2]); o2[3] = fma2(h2, u1.y, o2[3]);
            o2[4] = fma2(h2, u2.x, o2[4]); o2[5] = fma2(h2, u2.y, o2[5]);
        }
    }
    float o[12];
#pragma unroll
    for (int k = 0; k < 6; k++) upk2(o2[k], o[2 * k], o[2 * k + 1]);

    // ---- pos/vel outputs ----
    float nvx = o[0], nvy = o[1];
    float npx = fmaf(nvx, DT, px);
    float npy = fmaf(nvy, DT, py);
    if (npx >= (float)GRID_SZ) npx -= (float)GRID_SZ; else if (npx < 0.f) npx += (float)GRID_SZ;
    if (npy >= (float)GRID_SZ) npy -= (float)GRID_SZ; else if (npy < 0.f) npy += (float)GRID_SZ;
    out[i]            = npx;
    out[N_AG + i]     = npy;
    out[2 * N_AG + i] = nvx;
    out[3 * N_AG + i] = nvy;

    // ---- deposit tail: stores only (cur already in registers) ----
    float* out_lat = out + 4 * N_AG;
    if (win) {
#pragma unroll
        for (int c = 0; c < NCH; c++)
            out_lat[(c << 20) | cell] = fmaxf(fmaf(DT, o[2 + c], cur[c]), 0.f) * DECAY;
        g_claim[cell] = -1;   // restore state for next graph replay
    }
}

extern "C" void kernel_launch(void* const* d_in, const int* in_sizes, int n_in,
                              void* d_out, int out_size) {
    const float* pos = (const float*)d_in[0];   // (2, N)
    const float* vel = (const float*)d_in[1];   // (2, N)
    const float* lat = (const float*)d_in[2];   // (8, 1024, 1024)
    const float* W1  = (const float*)d_in[3];   // (24, 64)
    const float* b1  = (const float*)d_in[4];   // (64,)
    const float* W2  = (const float*)d_in[5];   // (64, 10)
    const float* b2  = (const float*)d_in[6];   // (10,)
    float* out = (float*)d_out;
    float* out_lat = out + 4 * N_AG;

    prep_kernel<<<GRID_SZ, 256>>>(lat, pos, out_lat);
    agent_kernel<<<N_AG / 256, 256>>>(pos, vel, W1, b1, W2, b2, lat, out);
}

// round 13
// speedup vs baseline: 1.0671x; 1.0671x over previous
#include <cuda_runtime.h>
#include <math.h>

#define N_AG 262144
#define GRID_SZ 1024
#define NCELL (GRID_SZ*GRID_SZ)
#define NCH 8
#define HID 64
#define DT 0.1f
#define DECAY 0.99f
#define SENSOR_LEN 3.0f
// cos(0.6), sin(0.6)
#define COS_A 0.825335614909678f
#define SIN_A 0.564642473395035f

typedef unsigned long long ull;

// Scratch (__device__ globals; no allocation allowed)
__device__ int    g_claim[NCELL];        // 4 MB : winning agent id per cell (reset by winners)
__device__ float4 g_boxA[NCELL];         // 16 MB: 3x3 box sums, channels 0-3
__device__ float4 g_boxB[NCELL];         // 16 MB: 3x3 box sums, channels 4-7

__device__ __forceinline__ ull pk2(float lo, float hi) {
    ull r; asm("mov.b64 %0, {%1, %2};" : "=l"(r) : "f"(lo), "f"(hi)); return r;
}
__device__ __forceinline__ void upk2(ull v, float& lo, float& hi) {
    asm("mov.b64 {%0, %1}, %2;" : "=f"(lo), "=f"(hi) : "l"(v));
}
__device__ __forceinline__ ull fma2(ull a, ull b, ull c) {
    ull d; asm("fma.rn.f32x2 %0, %1, %2, %3;" : "=l"(d) : "l"(a), "l"(b), "l"(c)); return d;
}

// FMA-pipe-only tanh (no MUFU): Eigen-style rational approx p(x)/q(x),
// reciprocal via integer magic + 3 Newton steps. |err| ~1e-6, clamp +-7.905.
__device__ __forceinline__ float fast_tanh(float x) {
    x = fminf(fmaxf(x, -7.90531110763549805f), 7.90531110763549805f);
    float x2 = x * x;
    float p = fmaf(x2, -2.76076847742355e-16f, 2.00018790482477e-13f);
    p = fmaf(p, x2, -8.60467152213735e-11f);
    p = fmaf(p, x2,  5.12229709037114e-08f);
    p = fmaf(p, x2,  1.48572235717979e-05f);
    p = fmaf(p, x2,  6.37261928875436e-04f);
    p = fmaf(p, x2,  4.89352455891786e-03f);
    p = p * x;
    float q = fmaf(x2, 1.19825839466702e-06f, 1.18534705686654e-04f);
    q = fmaf(q, x2, 2.26843463243900e-03f);
    q = fmaf(q, x2, 4.89352518554385e-03f);
    // q in [0.0049, ~0.9]: magic-constant reciprocal + Newton (no MUFU RCP)
    float r = __uint_as_float(0x7EF311C3u - __float_as_uint(q));
    r = r * fmaf(-q, r, 2.0f);
    r = r * fmaf(-q, r, 2.0f);
    r = r * fmaf(-q, r, 2.0f);
    return p * r;
}

// Pass 0: block = one lattice row. Coalesced float4 loads -> column sums in smem,
// decayed output, coalesced box-sum stores (stride-256 cell remap).
// Also: this thread claims agent tid's deposit cell (atomicMax, last-id-wins).
__global__ __launch_bounds__(256) void prep_kernel(const float* __restrict__ lat,
                                                   const float* __restrict__ pos,
                                                   float* __restrict__ out_lat) {
    __shared__ float cs_s[NCH][GRID_SZ];
    int x = blockIdx.x;
    int t = threadIdx.x;
    int y0 = t << 2;
    int r0 = ((x + 1023) & 1023) << 10;
    int r1 = x << 10;
    int r2 = ((x + 1) & 1023) << 10;

    // agent claim (one agent per prep thread; coalesced pos read)
    int a = blockIdx.x * 256 + t;
    float pax = pos[a], pay = pos[N_AG + a];
    int ca = ((((int)rintf(pax)) & 1023) << 10) | (((int)rintf(pay)) & 1023);
    atomicMax(&g_claim[ca], a);

#pragma unroll
    for (int c = 0; c < NCH; c++) {
        const float* L = lat + ((size_t)c << 20);
        float4 va = __ldg((const float4*)&L[r0 | y0]);
        float4 vb = __ldg((const float4*)&L[r1 | y0]);
        float4 vd = __ldg((const float4*)&L[r2 | y0]);
        *reinterpret_cast<float4*>(&cs_s[c][y0]) =
            make_float4(va.x + vb.x + vd.x, va.y + vb.y + vd.y,
                        va.z + vb.z + vd.z, va.w + vb.w + vd.w);
        *reinterpret_cast<float4*>(&out_lat[((size_t)c << 20) | (r1 | y0)]) =
            make_float4(vb.x * DECAY, vb.y * DECAY, vb.z * DECAY, vb.w * DECAY);
    }
    __syncthreads();

#pragma unroll
    for (int i = 0; i < 4; i++) {
        int y  = t + (i << 8);               // stride-256 cell ownership
        int ym = (y + 1023) & 1023;
        int yp = (y + 1) & 1023;
        float v[NCH];
#pragma unroll
        for (int c = 0; c < NCH; c++)
            v[c] = cs_s[c][ym] + cs_s[c][y] + cs_s[c][yp];
        int cell = r1 | y;
        g_boxA[cell] = make_float4(v[0], v[1], v[2], v[3]);   // 16B lane stride
        g_boxB[cell] = make_float4(v[4], v[5], v[6], v[7]);
    }
}

// Pass 1: one agent per thread (R9 structure), f32x2 MLP, FMA-only tanh,
// fused winner-deposit at tail.
__global__ __launch_bounds__(256, 3) void agent_kernel(
    const float* __restrict__ pos, const float* __restrict__ vel,
    const float* __restrict__ W1, const float* __restrict__ b1,
    const float* __restrict__ W2, const float* __restrict__ b2,
    const float* __restrict__ lat, float* __restrict__ out) {
    __shared__ float sW1[24 * HID];    // row-major [k][j]: natural (w_j,w_j+1) pairs
    __shared__ float sW2p[HID * 12];   // padded [j][12]
    __shared__ float sb1[HID];
    __shared__ float sO0[12];
    int t = threadIdx.x;
    for (int i = t; i < 24 * HID; i += 256) sW1[i] = W1[i];
    for (int i = t; i < HID * 12; i += 256) { int j = i / 12, k = i - j * 12; sW2p[i] = (k < 10) ? W2[j * 10 + k] : 0.f; }
    if (t < HID) sb1[t] = b1[t];
    if (t < 12)  sO0[t] = (t < 10) ? b2[t] : 0.f;
    __syncthreads();

    int i = blockIdx.x * 256 + t;
    float px = pos[i], py = pos[N_AG + i];
    float vx = vel[i], vy = vel[N_AG + i];

    // direction via normalization + angle-addition
    float invn = rsqrtf(fmaf(vx, vx, vy * vy));
    float c0 = vx * invn, s0 = vy * invn;
    float csv[3], snv[3];
    csv[0] = c0;                        snv[0] = s0;
    csv[1] = c0 * COS_A - s0 * SIN_A;   snv[1] = s0 * COS_A + c0 * SIN_A;
    csv[2] = c0 * COS_A + s0 * SIN_A;   snv[2] = s0 * COS_A - c0 * SIN_A;

    float xa[24];
#pragma unroll
    for (int s = 0; s < 3; s++) {
        int cx = (int)rintf(fmaf(SENSOR_LEN, csv[s], px));
        int cy = (int)rintf(fmaf(SENSOR_LEN, snv[s], py));
        int cell = ((cx & (GRID_SZ - 1)) << 10) | (cy & (GRID_SZ - 1));
        float4 a0 = __ldg(&g_boxA[cell]);
        float4 a1 = __ldg(&g_boxB[cell]);
        xa[s * 8 + 0] = a0.x; xa[s * 8 + 1] = a0.y; xa[s * 8 + 2] = a0.z; xa[s * 8 + 3] = a0.w;
        xa[s * 8 + 4] = a1.x; xa[s * 8 + 5] = a1.y; xa[s * 8 + 6] = a1.z; xa[s * 8 + 7] = a1.w;
    }

    // ---- MLP: 4 hidden units per block iter, f32x2 pairs ----
    ull o2[6];
#pragma unroll
    for (int k = 0; k < 6; k++) o2[k] = pk2(sO0[2 * k], sO0[2 * k + 1]);

#pragma unroll 1
    for (int j = 0; j < HID; j += 4) {
        ulonglong2 bu = *reinterpret_cast<const ulonglong2*>(&sb1[j]);
        ull a01 = bu.x, a23 = bu.y;
#pragma unroll
        for (int k = 0; k < 24; k++) {
            ulonglong2 wu = *reinterpret_cast<const ulonglong2*>(&sW1[k * HID + j]);
            ull x2 = pk2(xa[k], xa[k]);          // ALU-pipe mov, overlaps FMA
            a01 = fma2(x2, wu.x, a01);
            a23 = fma2(x2, wu.y, a23);
        }
        float hv[4];
        upk2(a01, hv[0], hv[1]);
        upk2(a23, hv[2], hv[3]);
#pragma unroll
        for (int jj = 0; jj < 4; jj++) {
            float h = fast_tanh(hv[jj]);          // FMA pipe, zero MUFU
            ull h2 = pk2(h, h);
            const ulonglong2* wp = reinterpret_cast<const ulonglong2*>(&sW2p[(j + jj) * 12]);
            ulonglong2 u0 = wp[0], u1 = wp[1], u2 = wp[2];
            o2[0] = fma2(h2, u0.x, o2[0]); o2[1] = fma2(h2, u0.y, o2[1]);
            o2[2] = fma2(h2, u1.x, o2[2]); o2[3] = fma2(h2, u1.y, o2[3]);
            o2[4] = fma2(h2, u2.x, o2[4]); o2[5] = fma2(h2, u2.y, o2[5]);
        }
    }
    float o[12];
#pragma unroll
    for (int k = 0; k < 6; k++) upk2(o2[k], o[2 * k], o[2 * k + 1]);

    // ---- pos/vel outputs ----
    float nvx = o[0], nvy = o[1];
    float npx = fmaf(nvx, DT, px);
    float npy = fmaf(nvy, DT, py);
    if (npx >= (float)GRID_SZ) npx -= (float)GRID_SZ; else if (npx < 0.f) npx += (float)GRID_SZ;
    if (npy >= (float)GRID_SZ) npy -= (float)GRID_SZ; else if (npy < 0.f) npy += (float)GRID_SZ;
    out[i]            = npx;
    out[N_AG + i]     = npy;
    out[2 * N_AG + i] = nvx;
    out[3 * N_AG + i] = nvy;

    // ---- fused deposit: winner writes relu(cur + DT*dp)*DECAY, resets claim ----
    float* out_lat = out + 4 * N_AG;
    int cell = ((((int)rintf(px)) & 1023) << 10) | (((int)rintf(py)) & 1023);
    if (g_claim[cell] == i) {
#pragma unroll
        for (int c = 0; c < NCH; c++) {
            float cur = __ldg(&lat[(c << 20) | cell]);
            out_lat[(c << 20) | cell] = fmaxf(fmaf(DT, o[2 + c], cur), 0.f) * DECAY;
        }
        g_claim[cell] = -1;   // restore state for next graph replay
    }
}

extern "C" void kernel_launch(void* const* d_in, const int* in_sizes, int n_in,
                              void* d_out, int out_size) {
    const float* pos = (const float*)d_in[0];   // (2, N)
    const float* vel = (const float*)d_in[1];   // (2, N)
    const float* lat = (const float*)d_in[2];   // (8, 1024, 1024)
    const float* W1  = (const float*)d_in[3];   // (24, 64)
    const float* b1  = (const float*)d_in[4];   // (64,)
    const float* W2  = (const float*)d_in[5];   // (64, 10)
    const float* b2  = (const float*)d_in[6];   // (10,)
    float* out = (float*)d_out;
    float* out_lat = out + 4 * N_AG;

    prep_kernel<<<GRID_SZ, 256>>>(lat, pos, out_lat);
    agent_kernel<<<N_AG / 256, 256>>>(pos, vel, W1, b1, W2, b2, lat, out);
}